// round 1
// baseline (speedup 1.0000x reference)
#include <cuda_runtime.h>

#define HID   256
#define LAT   128
#define ODIM  128
#define NBLK  4
#define NIT   10
#define TM    64
#define KC    32
#define NTHR  256
#define SMEM_BYTES ((2 * TM * HID + 2 * KC * HID) * 4)

typedef unsigned long long ull;

__device__ __forceinline__ ull pk2(float lo, float hi) {
    ull r; asm("mov.b64 %0, {%1, %2};" : "=l"(r) : "f"(lo), "f"(hi)); return r;
}
__device__ __forceinline__ void upk2(ull v, float& lo, float& hi) {
    asm("mov.b64 {%0, %1}, %2;" : "=f"(lo), "=f"(hi) : "l"(v));
}
__device__ __forceinline__ void fma2(ull& d, ull a, ull b) {
    asm("fma.rn.f32x2 %0, %1, %2, %0;" : "+l"(d) : "l"(a), "l"(b));
}

// One [TM x HID] = [TM x nk] @ [nk x HID] GEMM with A resident in SMEM (xs),
// weights streamed from global through a double-buffered SMEM chunk (ws).
// mode 0: out = acc + bias
// mode 1: out = relu(acc + bias)
// mode 2: out = ys - (acc + bias)
// Result is written back into xs. All threads participate (uniform control flow).
__device__ __noinline__ void gemm_hidden(
    float* xs, const float* ys, float* ws,
    const float* __restrict__ W, const float* __restrict__ bias,
    int nk, int mode, int r0, int c0, int tid)
{
    ull acc[8][4];
#pragma unroll
    for (int i = 0; i < 8; i++)
#pragma unroll
        for (int p = 0; p < 4; p++) acc[i][p] = 0ULL;

    const int nch = nk / KC;

    // prefetch chunk 0
    float4 pre[8];
    {
        const float4* src = (const float4*)W;
#pragma unroll
        for (int j = 0; j < 8; j++) pre[j] = src[tid + j * NTHR];
        float4* dst = (float4*)ws;
#pragma unroll
        for (int j = 0; j < 8; j++) dst[tid + j * NTHR] = pre[j];
    }
    __syncthreads();

    for (int c = 0; c < nch; c++) {
        const float* buf = ws + (c & 1) * (KC * HID);
        if (c + 1 < nch) {
            const float4* src = (const float4*)(W + (size_t)(c + 1) * KC * HID);
#pragma unroll
            for (int j = 0; j < 8; j++) pre[j] = src[tid + j * NTHR];
        }
        const float* xbase = xs + c * KC;
#pragma unroll
        for (int k4 = 0; k4 < KC / 4; k4++) {
            float4 a[8];
#pragma unroll
            for (int i = 0; i < 8; i++)
                a[i] = *(const float4*)(xbase + (r0 + i) * HID + k4 * 4);
#pragma unroll
            for (int kk = 0; kk < 4; kk++) {
                const float* wr = buf + (k4 * 4 + kk) * HID + c0;
                ulonglong2 b01 = *(const ulonglong2*)wr;        // (w0,w1),(w2,w3)
                ulonglong2 b23 = *(const ulonglong2*)(wr + 4);  // (w4,w5),(w6,w7)
#pragma unroll
                for (int i = 0; i < 8; i++) {
                    float av = (kk == 0) ? a[i].x : (kk == 1) ? a[i].y
                             : (kk == 2) ? a[i].z : a[i].w;
                    ull A2 = pk2(av, av);
                    fma2(acc[i][0], A2, b01.x);
                    fma2(acc[i][1], A2, b01.y);
                    fma2(acc[i][2], A2, b23.x);
                    fma2(acc[i][3], A2, b23.y);
                }
            }
        }
        if (c + 1 < nch) {
            float4* dst = (float4*)(ws + ((c + 1) & 1) * (KC * HID));
#pragma unroll
            for (int j = 0; j < 8; j++) dst[tid + j * NTHR] = pre[j];
        }
        __syncthreads();
    }

    // epilogue: bias + activation, write back to xs
    float4 bv0 = *(const float4*)(bias + c0);
    float4 bv1 = *(const float4*)(bias + c0 + 4);
    float bb[8] = {bv0.x, bv0.y, bv0.z, bv0.w, bv1.x, bv1.y, bv1.z, bv1.w};
#pragma unroll
    for (int i = 0; i < 8; i++) {
        float v[8];
#pragma unroll
        for (int p = 0; p < 4; p++) upk2(acc[i][p], v[2 * p], v[2 * p + 1]);
#pragma unroll
        for (int j = 0; j < 8; j++) v[j] += bb[j];
        if (mode == 1) {
#pragma unroll
            for (int j = 0; j < 8; j++) v[j] = fmaxf(v[j], 0.0f);
        } else if (mode == 2) {
            const float* yr = ys + (r0 + i) * HID + c0;
            float4 y0 = *(const float4*)yr;
            float4 y1 = *(const float4*)(yr + 4);
            v[0] = y0.x - v[0]; v[1] = y0.y - v[1];
            v[2] = y0.z - v[2]; v[3] = y0.w - v[3];
            v[4] = y1.x - v[4]; v[5] = y1.y - v[5];
            v[6] = y1.z - v[6]; v[7] = y1.w - v[7];
        }
        float* xr = xs + (r0 + i) * HID + c0;
        *(float4*)xr       = make_float4(v[0], v[1], v[2], v[3]);
        *(float4*)(xr + 4) = make_float4(v[4], v[5], v[6], v[7]);
    }
    __syncthreads();
}

// Final GEMM: out[TM x ODIM] = xs[TM x HID] @ W[HID x ODIM] + bias, to global.
__device__ __noinline__ void gemm_final(
    const float* xs, float* ws,
    const float* __restrict__ W, const float* __restrict__ bias,
    float* __restrict__ out, int row_base, int r0, int lane, int tid)
{
    ull acc[8][2];
#pragma unroll
    for (int i = 0; i < 8; i++) { acc[i][0] = 0ULL; acc[i][1] = 0ULL; }

    const int c0 = lane * 4;
    const int nch = HID / KC;  // 8

    float4 pre[4];
    {
        const float4* src = (const float4*)W;
#pragma unroll
        for (int j = 0; j < 4; j++) pre[j] = src[tid + j * NTHR];
        float4* dst = (float4*)ws;
#pragma unroll
        for (int j = 0; j < 4; j++) dst[tid + j * NTHR] = pre[j];
    }
    __syncthreads();

    for (int c = 0; c < nch; c++) {
        const float* buf = ws + (c & 1) * (KC * ODIM);
        if (c + 1 < nch) {
            const float4* src = (const float4*)(W + (size_t)(c + 1) * KC * ODIM);
#pragma unroll
            for (int j = 0; j < 4; j++) pre[j] = src[tid + j * NTHR];
        }
        const float* xbase = xs + c * KC;
#pragma unroll
        for (int k4 = 0; k4 < KC / 4; k4++) {
            float4 a[8];
#pragma unroll
            for (int i = 0; i < 8; i++)
                a[i] = *(const float4*)(xbase + (r0 + i) * HID + k4 * 4);
#pragma unroll
            for (int kk = 0; kk < 4; kk++) {
                const float* wr = buf + (k4 * 4 + kk) * ODIM + c0;
                ulonglong2 b01 = *(const ulonglong2*)wr;
#pragma unroll
                for (int i = 0; i < 8; i++) {
                    float av = (kk == 0) ? a[i].x : (kk == 1) ? a[i].y
                             : (kk == 2) ? a[i].z : a[i].w;
                    ull A2 = pk2(av, av);
                    fma2(acc[i][0], A2, b01.x);
                    fma2(acc[i][1], A2, b01.y);
                }
            }
        }
        if (c + 1 < nch) {
            float4* dst = (float4*)(ws + ((c + 1) & 1) * (KC * ODIM));
#pragma unroll
            for (int j = 0; j < 4; j++) dst[tid + j * NTHR] = pre[j];
        }
        __syncthreads();
    }

    float4 bv = *(const float4*)(bias + c0);
#pragma unroll
    for (int i = 0; i < 8; i++) {
        float v0, v1, v2, v3;
        upk2(acc[i][0], v0, v1);
        upk2(acc[i][1], v2, v3);
        v0 += bv.x; v1 += bv.y; v2 += bv.z; v3 += bv.w;
        *(float4*)(out + (size_t)(row_base + r0 + i) * ODIM + c0)
            = make_float4(v0, v1, v2, v3);
    }
}

__global__ void __launch_bounds__(NTHR, 1)
inv_resnet_kernel(
    const float* __restrict__ x,
    const float* __restrict__ W_init, const float* __restrict__ b_init,
    const float* __restrict__ Wg1,    const float* __restrict__ bg1,
    const float* __restrict__ Wg2,    const float* __restrict__ bg2,
    const float* __restrict__ W_final, const float* __restrict__ b_final,
    float* __restrict__ out)
{
    extern __shared__ float sm[];
    float* xs = sm;                 // [TM][HID] current state (A operand + result)
    float* ys = sm + TM * HID;      // [TM][HID] block input y
    float* ws = sm + 2 * TM * HID;  // [2][KC][HID] weight double buffer

    const int tid  = threadIdx.x;
    const int lane = tid & 31;
    const int wrp  = tid >> 5;
    const int r0   = wrp * 8;       // 8 rows per thread (warp = row group)
    const int c0   = lane * 8;      // 8 cols per thread (lane = col group)
    const int row_base = blockIdx.x * TM;

    // Load x tile [TM x LAT] into xs (row stride HID)
    {
        const int nf4 = TM * LAT / 4;  // 2048
        for (int i = tid; i < nf4; i += NTHR) {
            int r  = i >> 5;           // LAT/4 = 32 float4 per row
            int c4 = i & 31;
            float4 v = ((const float4*)(x + (size_t)(row_base + r) * LAT))[c4];
            *(float4*)(xs + r * HID + c4 * 4) = v;
        }
    }
    __syncthreads();

    // h = x @ W_init + b_init
    gemm_hidden(xs, ys, ws, W_init, b_init, LAT, 0, r0, c0, tid);

    for (int b = 0; b < NBLK; b++) {
        // y = h (copy xs -> ys); x starts at y
#pragma unroll
        for (int j = 0; j < (TM * HID / 4) / NTHR; j++)
            ((float4*)ys)[tid + j * NTHR] = ((const float4*)xs)[tid + j * NTHR];
        __syncthreads();

        const float* W1 = Wg1 + (size_t)b * HID * HID;
        const float* W2 = Wg2 + (size_t)b * HID * HID;
        const float* b1 = bg1 + b * HID;
        const float* b2 = bg2 + b * HID;

        for (int it = 0; it < NIT; it++) {
            gemm_hidden(xs, ys, ws, W1, b1, HID, 1, r0, c0, tid);  // t = relu(x@W1+b1)
            gemm_hidden(xs, ys, ws, W2, b2, HID, 2, r0, c0, tid);  // x = y - (t@W2+b2)
        }
    }

    // out = h @ W_final + b_final
    gemm_final(xs, ws, W_final, b_final, out, row_base, r0, lane, tid);
}

extern "C" void kernel_launch(void* const* d_in, const int* in_sizes, int n_in,
                              void* d_out, int out_size)
{
    const float* x       = (const float*)d_in[0];
    const float* W_init  = (const float*)d_in[1];
    const float* b_init  = (const float*)d_in[2];
    const float* Wg1     = (const float*)d_in[3];
    const float* bg1     = (const float*)d_in[4];
    const float* Wg2     = (const float*)d_in[5];
    const float* bg2     = (const float*)d_in[6];
    const float* W_final = (const float*)d_in[7];
    const float* b_final = (const float*)d_in[8];
    float* out = (float*)d_out;

    const int batch = in_sizes[0] / LAT;

    cudaFuncSetAttribute(inv_resnet_kernel,
                         cudaFuncAttributeMaxDynamicSharedMemorySize, SMEM_BYTES);

    dim3 grid(batch / TM);
    inv_resnet_kernel<<<grid, NTHR, SMEM_BYTES>>>(
        x, W_init, b_init, Wg1, bg1, Wg2, bg2, W_final, b_final, out);
}